// round 6
// baseline (speedup 1.0000x reference)
#include <cuda_runtime.h>
#include <cstdint>

// UpsampleLayer2D quadrant depth-to-space:
// out[b, r2, c2, co] = x[b, r2%R, c2%C, 4*co + k],  k = 2*(r2>=R) + (c2>=C)
// B=32, R=C=200, Cin=64, Co=16.
//
// R5: back to the best shape (R2: one work-item per thread, block 512,
// one-shot grid — the persistent variant regressed because grid-stride
// serializes memory across iterations). Policy change vs R2: keep streaming
// loads (__ldcs, don't pollute L2 with a touch-once 328MB read stream) but
// use DEFAULT write-back stores so the LTS write-coalescer can batch the four
// store streams into full-line drains instead of evicting each line eagerly.

static constexpr int B  = 32;
static constexpr int R  = 200;
static constexpr int C  = 200;
static constexpr int CO = 16;            // output channels
static constexpr unsigned PIX = B * R * C;          // 1,280,000 pixels
static constexpr unsigned NTHREADS = PIX * 4;       // 5,120,000 (co groups of 4)

// float4 strides in the output [B, 2R, 2C, CO]:
static constexpr size_t OUT_ROW_F4  = (size_t)(2 * C) * CO / 4;   // 1600
static constexpr size_t Q_COL_OFF   = (size_t)C * CO / 4;         // 800
static constexpr size_t Q_ROW_OFF   = (size_t)R * OUT_ROW_F4;     // 320000

__global__ __launch_bounds__(512) void upsample2d_kernel(
    const float4* __restrict__ x4, float4* __restrict__ out4)
{
    unsigned g = blockIdx.x * 512u + threadIdx.x;   // grid sized exactly
    unsigned co4 = g & 3u;          // which group of 4 output channels
    unsigned pix = g >> 2;          // input pixel index

    unsigned c  = pix % (unsigned)C;
    unsigned rb = pix / (unsigned)C;
    unsigned r  = rb % (unsigned)R;
    unsigned b  = rb / (unsigned)R;

    const float4* src = x4 + (size_t)pix * 16 + (size_t)co4 * 4;
    float4 v0 = __ldcs(src + 0);
    float4 v1 = __ldcs(src + 1);
    float4 v2 = __ldcs(src + 2);
    float4 v3 = __ldcs(src + 3);

    size_t opix = ((size_t)b * (2 * R) + r) * (2 * C) + c;  // quadrant-0 pixel
    size_t o0   = opix * 4 + co4;                            // float4 index

    out4[o0]                         = make_float4(v0.x, v1.x, v2.x, v3.x); // TL
    out4[o0 + Q_COL_OFF]             = make_float4(v0.y, v1.y, v2.y, v3.y); // TR
    out4[o0 + Q_ROW_OFF]             = make_float4(v0.z, v1.z, v2.z, v3.z); // BL
    out4[o0 + Q_ROW_OFF + Q_COL_OFF] = make_float4(v0.w, v1.w, v2.w, v3.w); // BR
}

extern "C" void kernel_launch(void* const* d_in, const int* in_sizes, int n_in,
                              void* d_out, int out_size)
{
    const float4* x4   = (const float4*)d_in[0];
    float4*       out4 = (float4*)d_out;

    // NTHREADS = 5,120,000 = 10000 * 512 exactly; no bounds check needed.
    upsample2d_kernel<<<NTHREADS / 512, 512>>>(x4, out4);
}

// round 7
// speedup vs baseline: 1.3369x; 1.3369x over previous
#include <cuda_runtime.h>
#include <cstdint>

// UpsampleLayer2D quadrant depth-to-space:
// out[b, r2, c2, co] = x[b, r2%R, c2%C, 4*co + k],  k = 2*(r2>=R) + (c2>=C)
// B=32, R=C=200, Cin=64, Co=16.
//
// R6: exact R2 body (the best: 98.2us, DRAM 83.8%) — one work item per
// thread, 4 front-batched LDG.128 + 4x4 register transpose + 4 STG.128,
// streaming policy on BOTH loads and stores (__ldcs/__stcs; R5 proved
// write-back stores cost 25%). Only change vs R2: block 1024 (block-size
// scan was monotone 256 -> 512; 30 regs keeps 64 resident warps/SM).

static constexpr int B  = 32;
static constexpr int R  = 200;
static constexpr int C  = 200;
static constexpr int CO = 16;            // output channels
static constexpr unsigned PIX = B * R * C;          // 1,280,000 pixels
static constexpr unsigned NTHREADS = PIX * 4;       // 5,120,000 (co groups of 4)

// float4 strides in the output [B, 2R, 2C, CO]:
static constexpr size_t OUT_ROW_F4  = (size_t)(2 * C) * CO / 4;   // 1600
static constexpr size_t Q_COL_OFF   = (size_t)C * CO / 4;         // 800
static constexpr size_t Q_ROW_OFF   = (size_t)R * OUT_ROW_F4;     // 320000

__global__ __launch_bounds__(1024) void upsample2d_kernel(
    const float4* __restrict__ x4, float4* __restrict__ out4)
{
    unsigned g = blockIdx.x * 1024u + threadIdx.x;  // grid sized exactly
    unsigned co4 = g & 3u;          // which group of 4 output channels
    unsigned pix = g >> 2;          // input pixel index

    unsigned c  = pix % (unsigned)C;
    unsigned rb = pix / (unsigned)C;
    unsigned r  = rb % (unsigned)R;
    unsigned b  = rb / (unsigned)R;

    const float4* src = x4 + (size_t)pix * 16 + (size_t)co4 * 4;
    float4 v0 = __ldcs(src + 0);
    float4 v1 = __ldcs(src + 1);
    float4 v2 = __ldcs(src + 2);
    float4 v3 = __ldcs(src + 3);

    size_t opix = ((size_t)b * (2 * R) + r) * (2 * C) + c;  // quadrant-0 pixel
    size_t o0   = opix * 4 + co4;                            // float4 index

    __stcs(out4 + o0,                         make_float4(v0.x, v1.x, v2.x, v3.x)); // TL
    __stcs(out4 + o0 + Q_COL_OFF,             make_float4(v0.y, v1.y, v2.y, v3.y)); // TR
    __stcs(out4 + o0 + Q_ROW_OFF,             make_float4(v0.z, v1.z, v2.z, v3.z)); // BL
    __stcs(out4 + o0 + Q_ROW_OFF + Q_COL_OFF, make_float4(v0.w, v1.w, v2.w, v3.w)); // BR
}

extern "C" void kernel_launch(void* const* d_in, const int* in_sizes, int n_in,
                              void* d_out, int out_size)
{
    const float4* x4   = (const float4*)d_in[0];
    float4*       out4 = (float4*)d_out;

    // NTHREADS = 5,120,000 = 5000 * 1024 exactly; no bounds check needed.
    upsample2d_kernel<<<NTHREADS / 1024, 1024>>>(x4, out4);
}

// round 8
// speedup vs baseline: 1.3373x; 1.0003x over previous
#include <cuda_runtime.h>
#include <cstdint>

// UpsampleLayer2D quadrant depth-to-space:
// out[b, r2, c2, co] = x[b, r2%R, c2%C, 4*co + k],  k = 2*(r2>=R) + (c2>=C)
// B=32, R=C=200, Cin=64, Co=16.
//
// R8: R2 config (one work item/thread, block 512, .cs loads + .cs stores --
// each knob validated as optimal in R2-R7) with the loads widened to
// Blackwell 256-bit accesses: 2x LDG.E.256 instead of 4x LDG.128. Same 64B
// per thread, same ~30 regs / occupancy, half the L1tex load wavefronts.

static constexpr int B  = 32;
static constexpr int R  = 200;
static constexpr int C  = 200;
static constexpr int CO = 16;            // output channels
static constexpr unsigned PIX = B * R * C;          // 1,280,000 pixels
static constexpr unsigned NTHREADS = PIX * 4;       // 5,120,000 (co groups of 4)

// float4 strides in the output [B, 2R, 2C, CO]:
static constexpr size_t OUT_ROW_F4  = (size_t)(2 * C) * CO / 4;   // 1600
static constexpr size_t Q_COL_OFF   = (size_t)C * CO / 4;         // 800
static constexpr size_t Q_ROW_OFF   = (size_t)R * OUT_ROW_F4;     // 320000

// 256-bit streaming load: two float4s in one LDG.E.256 (sm_100+).
__device__ __forceinline__ void ldg256_cs(const float4* p, float4& a, float4& b)
{
    asm volatile(
        "ld.global.cs.v8.b32 {%0,%1,%2,%3,%4,%5,%6,%7}, [%8];"
        : "=r"(*(uint32_t*)&a.x), "=r"(*(uint32_t*)&a.y),
          "=r"(*(uint32_t*)&a.z), "=r"(*(uint32_t*)&a.w),
          "=r"(*(uint32_t*)&b.x), "=r"(*(uint32_t*)&b.y),
          "=r"(*(uint32_t*)&b.z), "=r"(*(uint32_t*)&b.w)
        : "l"(p));
}

__global__ __launch_bounds__(512) void upsample2d_kernel(
    const float4* __restrict__ x4, float4* __restrict__ out4)
{
    unsigned g = blockIdx.x * 512u + threadIdx.x;   // grid sized exactly
    unsigned co4 = g & 3u;          // which group of 4 output channels
    unsigned pix = g >> 2;          // input pixel index

    unsigned c  = pix % (unsigned)C;
    unsigned rb = pix / (unsigned)C;
    unsigned r  = rb % (unsigned)R;
    unsigned b  = rb / (unsigned)R;

    // src is 64B-aligned (float4 index pix*16 + co4*4 is a multiple of 4).
    const float4* src = x4 + (size_t)pix * 16 + (size_t)co4 * 4;
    float4 v0, v1, v2, v3;
    ldg256_cs(src + 0, v0, v1);
    ldg256_cs(src + 2, v2, v3);

    size_t opix = ((size_t)b * (2 * R) + r) * (2 * C) + c;  // quadrant-0 pixel
    size_t o0   = opix * 4 + co4;                            // float4 index

    __stcs(out4 + o0,                         make_float4(v0.x, v1.x, v2.x, v3.x)); // TL
    __stcs(out4 + o0 + Q_COL_OFF,             make_float4(v0.y, v1.y, v2.y, v3.y)); // TR
    __stcs(out4 + o0 + Q_ROW_OFF,             make_float4(v0.z, v1.z, v2.z, v3.z)); // BL
    __stcs(out4 + o0 + Q_ROW_OFF + Q_COL_OFF, make_float4(v0.w, v1.w, v2.w, v3.w)); // BR
}

extern "C" void kernel_launch(void* const* d_in, const int* in_sizes, int n_in,
                              void* d_out, int out_size)
{
    const float4* x4   = (const float4*)d_in[0];
    float4*       out4 = (float4*)d_out;

    // NTHREADS = 5,120,000 = 10000 * 512 exactly; no bounds check needed.
    upsample2d_kernel<<<NTHREADS / 512, 512>>>(x4, out4);
}

// round 9
// speedup vs baseline: 1.3378x; 1.0003x over previous
#include <cuda_runtime.h>
#include <cstdint>

// UpsampleLayer2D quadrant depth-to-space:
// out[b, r2, c2, co] = x[b, r2%R, c2%C, 4*co + k],  k = 2*(r2>=R) + (c2>=C)
// B=32, R=C=200, Cin=64, Co=16.
//
// FINAL (== R2, the measured optimum across the full knob matrix):
//  - one work item (pixel x 4-output-channel group) per thread
//  - 4 front-batched LDG.128: warp reads 2KB fully contiguous
//  - 4x4 register transpose (no smem, no syncs)
//  - 4 STG.128, one per quadrant: warp writes 512B contiguous per quadrant,
//    full-line coverage -> no read-for-ownership
//  - streaming policy on BOTH sides (__ldcs/__stcs). Write-back stores cost
//    25% (R5); both tensors are ~328MB touch-once >> 126MB L2.
//  - block 512, one-shot grid sized exactly (10000 x 512), 30 regs.
// Measured: 98.2us, DRAM 83.8% / 7.2 TB/s combined -- the mixed-R/W HBM
// turnaround ceiling for this 655MB single-pass shuffle. MLP=8 (-occupancy),
// persistent grid (-11%), block 256/1024, LDG.256: all measured <= this.

static constexpr int B  = 32;
static constexpr int R  = 200;
static constexpr int C  = 200;
static constexpr int CO = 16;            // output channels
static constexpr unsigned PIX = B * R * C;          // 1,280,000 pixels
static constexpr unsigned NTHREADS = PIX * 4;       // 5,120,000 (co groups of 4)

// float4 strides in the output [B, 2R, 2C, CO]:
static constexpr size_t OUT_ROW_F4  = (size_t)(2 * C) * CO / 4;   // 1600
static constexpr size_t Q_COL_OFF   = (size_t)C * CO / 4;         // 800
static constexpr size_t Q_ROW_OFF   = (size_t)R * OUT_ROW_F4;     // 320000

__global__ __launch_bounds__(512) void upsample2d_kernel(
    const float4* __restrict__ x4, float4* __restrict__ out4)
{
    unsigned g = blockIdx.x * 512u + threadIdx.x;   // grid sized exactly
    unsigned co4 = g & 3u;          // which group of 4 output channels
    unsigned pix = g >> 2;          // input pixel index

    unsigned c  = pix % (unsigned)C;
    unsigned rb = pix / (unsigned)C;
    unsigned r  = rb % (unsigned)R;
    unsigned b  = rb / (unsigned)R;

    const float4* src = x4 + (size_t)pix * 16 + (size_t)co4 * 4;
    float4 v0 = __ldcs(src + 0);
    float4 v1 = __ldcs(src + 1);
    float4 v2 = __ldcs(src + 2);
    float4 v3 = __ldcs(src + 3);

    size_t opix = ((size_t)b * (2 * R) + r) * (2 * C) + c;  // quadrant-0 pixel
    size_t o0   = opix * 4 + co4;                            // float4 index

    __stcs(out4 + o0,                         make_float4(v0.x, v1.x, v2.x, v3.x)); // TL
    __stcs(out4 + o0 + Q_COL_OFF,             make_float4(v0.y, v1.y, v2.y, v3.y)); // TR
    __stcs(out4 + o0 + Q_ROW_OFF,             make_float4(v0.z, v1.z, v2.z, v3.z)); // BL
    __stcs(out4 + o0 + Q_ROW_OFF + Q_COL_OFF, make_float4(v0.w, v1.w, v2.w, v3.w)); // BR
}

extern "C" void kernel_launch(void* const* d_in, const int* in_sizes, int n_in,
                              void* d_out, int out_size)
{
    const float4* x4   = (const float4*)d_in[0];
    float4*       out4 = (float4*)d_out;

    // NTHREADS = 5,120,000 = 10000 * 512 exactly; no bounds check needed.
    upsample2d_kernel<<<NTHREADS / 512, 512>>>(x4, out4);
}